// round 1
// baseline (speedup 1.0000x reference)
#include <cuda_runtime.h>
#include <cuda_bf16.h>
#include <cstdint>

// Problem constants (match reference)
#define N_NODES 50000
#define N_EDGES 800000
#define IN_DIM  256
#define H1      512
#define H2      128
#define M_PAD   50048   // round up to multiple of 128 for guard-free GEMM

// -------------------- scratch (device globals; no allocs) --------------------
__device__ float g_deg [N_NODES];
__device__ float g_dinv[N_NODES];
__device__ float g_agg1[(size_t)M_PAD * IN_DIM];   // A_norm @ x        [50048,256]
__device__ float g_feat1[(size_t)M_PAD * H1];      // prelu(agg1@W1+b1) [50048,512]
__device__ float g_xw2 [(size_t)M_PAD * H2];       // feat1@W2          [50048,128]

// -------------------- small elementwise kernels --------------------
__global__ void deg_init(float* deg, int n) {
    int i = blockIdx.x * blockDim.x + threadIdx.x;
    if (i < n) deg[i] = 1.0f;   // self-loop weight
}

__global__ void deg_accum(const int* __restrict__ col, const float* __restrict__ ew,
                          float* deg, int E) {
    int e = blockIdx.x * blockDim.x + threadIdx.x;
    if (e < E) atomicAdd(&deg[col[e]], ew[e]);
}

__global__ void deg_rsqrt(const float* __restrict__ deg, float* dinv, int n) {
    int i = blockIdx.x * blockDim.x + threadIdx.x;
    if (i < n) {
        float d = deg[i];
        dinv[i] = d > 0.f ? rsqrtf(d) : 0.f;
    }
}

// dst[i,:] = dinv[i]^2 * src[i,:]   (self-loop term), float4-vectorized
__global__ void selfloop_init(const float4* __restrict__ src, float4* __restrict__ dst,
                              const float* __restrict__ dinv, int n_nodes, int d4) {
    long idx = (long)blockIdx.x * blockDim.x + threadIdx.x;
    long total = (long)n_nodes * d4;
    if (idx >= total) return;
    int node = (int)(idx / d4);
    float s = dinv[node]; s = s * s;
    float4 v = src[idx];
    dst[idx] = make_float4(s * v.x, s * v.y, s * v.z, s * v.w);
}

// -------------------- edge aggregation (warp per edge) --------------------
// dst[col] += (dinv[row]*ew*dinv[col]) * src[row]   via RED.E.ADD.F32
template <int D>  // D in {256,128}; D/4 float4 per row, lanes stride 32
__global__ void agg_edges(const float4* __restrict__ src, float* __restrict__ dst,
                          const int* __restrict__ row, const int* __restrict__ col,
                          const float* __restrict__ ew, const float* __restrict__ dinv,
                          int E) {
    int e = (int)(((long)blockIdx.x * blockDim.x + threadIdx.x) >> 5);
    if (e >= E) return;
    int lane = threadIdx.x & 31;
    int r = row[e], c = col[e];
    float s = dinv[r] * ew[e] * dinv[c];
    const float4* srow = src + (size_t)r * (D / 4);
    float* drow = dst + (size_t)c * D;
#pragma unroll
    for (int i = 0; i < D / 128; i++) {
        int q = lane + i * 32;       // float4 index within the row
        float4 v = srow[q];
        int d = q * 4;
        atomicAdd(drow + d + 0, s * v.x);
        atomicAdd(drow + d + 1, s * v.y);
        atomicAdd(drow + d + 2, s * v.z);
        atomicAdd(drow + d + 3, s * v.w);
    }
}

// -------------------- SGEMM 128x128x8, 8x8 per thread, 256 threads ----------
// C[M,N] = A[M,K] @ B[K,N]; optional fused epilogue: C = prelu(C + bias)
// Requires M%128==0, N%128==0, K%8==0 (guaranteed by padding).
__global__ __launch_bounds__(256)
void sgemm_kernel(const float* __restrict__ A, const float* __restrict__ B,
                  float* __restrict__ C, int M, int N, int K,
                  const float* __restrict__ bias, const float* __restrict__ alpha) {
    constexpr int BM = 128, BN = 128, BK = 8, TM = 8, TN = 8;
    __shared__ float As[BK][BM];
    __shared__ float Bs[BK][BN];

    const int tid  = threadIdx.x;
    const int crow = tid / (BN / TN);   // 0..15
    const int ccol = tid % (BN / TN);   // 0..15

    const float* Ab = A + (size_t)blockIdx.y * BM * K;
    const float* Bb = B + (size_t)blockIdx.x * BN;

    // A tile load mapping: 128 rows x 8 cols = 256 float4 (thread -> row=tid/2, k4=(tid&1)*4)
    const int arow = tid >> 1;
    const int ak   = (tid & 1) * 4;
    // B tile load mapping: 8 rows x 128 cols = 256 float4 (thread -> row=tid/32, col=(tid&31)*4)
    const int brow = tid >> 5;
    const int bcol = (tid & 31) * 4;

    float acc[TM][TN] = {};

    for (int k0 = 0; k0 < K; k0 += BK) {
        float4 a = *(const float4*)(Ab + (size_t)arow * K + k0 + ak);
        As[ak + 0][arow] = a.x;
        As[ak + 1][arow] = a.y;
        As[ak + 2][arow] = a.z;
        As[ak + 3][arow] = a.w;
        *(float4*)&Bs[brow][bcol] = *(const float4*)(Bb + (size_t)(k0 + brow) * N + bcol);
        __syncthreads();

#pragma unroll
        for (int k = 0; k < BK; k++) {
            float ar[TM], br[TN];
#pragma unroll
            for (int i = 0; i < TM; i++) ar[i] = As[k][crow * TM + i];
#pragma unroll
            for (int j = 0; j < TN; j++) br[j] = Bs[k][ccol * TN + j];
#pragma unroll
            for (int i = 0; i < TM; i++)
#pragma unroll
                for (int j = 0; j < TN; j++)
                    acc[i][j] = fmaf(ar[i], br[j], acc[i][j]);
        }
        __syncthreads();
    }

    const float al = alpha ? alpha[0] : 0.f;
    float* Cb = C + (size_t)blockIdx.y * BM * N + (size_t)blockIdx.x * BN;
#pragma unroll
    for (int i = 0; i < TM; i++) {
        const int r = crow * TM + i;
#pragma unroll
        for (int j = 0; j < TN; j += 4) {
            const int c = ccol * TN + j;
            float4 v = make_float4(acc[i][j], acc[i][j + 1], acc[i][j + 2], acc[i][j + 3]);
            if (bias) {
                const int gc = blockIdx.x * BN + c;
                v.x += bias[gc + 0]; v.y += bias[gc + 1];
                v.z += bias[gc + 2]; v.w += bias[gc + 3];
                v.x = v.x >= 0.f ? v.x : al * v.x;
                v.y = v.y >= 0.f ? v.y : al * v.y;
                v.z = v.z >= 0.f ? v.z : al * v.z;
                v.w = v.w >= 0.f ? v.w : al * v.w;
            }
            *(float4*)(Cb + (size_t)r * N + c) = v;
        }
    }
}

// out = prelu(out + b2) over [N_NODES, H2], float4-vectorized (H2%4==0)
__global__ void finalize_kernel(float4* __restrict__ out, const float* __restrict__ b2,
                                const float* __restrict__ alpha, long n4) {
    long i = (long)blockIdx.x * blockDim.x + threadIdx.x;
    if (i >= n4) return;
    float4 v = out[i];
    int d = (int)((i * 4) & (H2 - 1));
    float a = alpha[0];
    v.x += b2[d + 0]; v.y += b2[d + 1]; v.z += b2[d + 2]; v.w += b2[d + 3];
    v.x = v.x >= 0.f ? v.x : a * v.x;
    v.y = v.y >= 0.f ? v.y : a * v.y;
    v.z = v.z >= 0.f ? v.z : a * v.z;
    v.w = v.w >= 0.f ? v.w : a * v.w;
    out[i] = v;
}

// -------------------- launch --------------------
extern "C" void kernel_launch(void* const* d_in, const int* in_sizes, int n_in,
                              void* d_out, int out_size) {
    // Input order: x, edge_attr, W1, b1, W2, b2, alpha, edge_index
    const float* x     = (const float*)d_in[0];
    const float* ew    = (const float*)d_in[1];
    const float* W1    = (const float*)d_in[2];
    const float* b1    = (const float*)d_in[3];
    const float* W2    = (const float*)d_in[4];
    const float* b2    = (const float*)d_in[5];
    const float* alpha = (const float*)d_in[6];
    const int*   eidx  = (const int*)  d_in[7];

    const int E = in_sizes[1];            // 800000
    const int N = in_sizes[0] / IN_DIM;   // 50000
    const int* row = eidx;
    const int* col = eidx + E;

    float* out = (float*)d_out;

    float *deg, *dinv, *agg1, *feat1, *xw2;
    cudaGetSymbolAddress((void**)&deg,   g_deg);
    cudaGetSymbolAddress((void**)&dinv,  g_dinv);
    cudaGetSymbolAddress((void**)&agg1,  g_agg1);
    cudaGetSymbolAddress((void**)&feat1, g_feat1);
    cudaGetSymbolAddress((void**)&xw2,   g_xw2);

    // 1) degrees + dinv
    deg_init<<<(N + 255) / 256, 256>>>(deg, N);
    deg_accum<<<(E + 255) / 256, 256>>>(col, ew, deg, E);
    deg_rsqrt<<<(N + 255) / 256, 256>>>(deg, dinv, N);

    // 2) layer-1 aggregation at D=256: agg1 = A_norm @ x
    {
        long n4 = (long)N * (IN_DIM / 4);
        selfloop_init<<<(int)((n4 + 255) / 256), 256>>>((const float4*)x, (float4*)agg1, dinv, N, IN_DIM / 4);
        long threads = (long)E * 32;
        agg_edges<IN_DIM><<<(int)((threads + 255) / 256), 256>>>(
            (const float4*)agg1, agg1, row, col, ew, dinv, 0);  // placeholder guard (see below)
    }
    // NOTE: src for edges must be the ORIGINAL x, not agg1 (aggregation is one-shot,
    // not iterative). Re-issue correctly: the call above was launched with E=0 (no-op).
    {
        long threads = (long)E * 32;
        agg_edges<IN_DIM><<<(int)((threads + 255) / 256), 256>>>(
            (const float4*)x, agg1, row, col, ew, dinv, E);
    }

    // 3) GEMM1: feat1 = prelu(agg1 @ W1 + b1)   [50048,256]x[256,512]
    {
        dim3 grid(H1 / 128, M_PAD / 128);
        sgemm_kernel<<<grid, 256>>>(agg1, W1, feat1, M_PAD, H1, IN_DIM, b1, alpha);
    }

    // 4) GEMM2: xw2 = feat1 @ W2               [50048,512]x[512,128]
    {
        dim3 grid(H2 / 128, M_PAD / 128);
        sgemm_kernel<<<grid, 256>>>(feat1, W2, xw2, M_PAD, H2, H1, nullptr, nullptr);
    }

    // 5) layer-2 aggregation at D=128 into d_out
    {
        long n4 = (long)N * (H2 / 4);
        selfloop_init<<<(int)((n4 + 255) / 256), 256>>>((const float4*)xw2, (float4*)out, dinv, N, H2 / 4);
        long threads = (long)E * 32;
        agg_edges<H2><<<(int)((threads + 255) / 256), 256>>>(
            (const float4*)xw2, out, row, col, ew, dinv, E);
    }

    // 6) out = prelu(out + b2)
    {
        long n4 = (long)N * (H2 / 4);
        finalize_kernel<<<(int)((n4 + 255) / 256), 256>>>((float4*)out, b2, alpha, n4);
    }
}

// round 2
// speedup vs baseline: 1.7354x; 1.7354x over previous
#include <cuda_runtime.h>
#include <cuda_bf16.h>
#include <cstdint>

#define N_NODES 50000
#define N_EDGES 800000
#define IN_DIM  256
#define H1      512
#define H2      128
#define M_PAD   50048   // multiple of 128 for guard-free GEMM

// -------------------- scratch --------------------
__device__ float g_deg [N_NODES];
__device__ float g_dinv[N_NODES];
__device__ float g_agg1[(size_t)M_PAD * IN_DIM];
__device__ float g_feat1[(size_t)M_PAD * H1];
__device__ float g_xw2 [(size_t)M_PAD * H2];

// -------------------- helpers --------------------
__device__ __forceinline__ void red_add_v4(float* addr, float a, float b, float c, float d) {
    asm volatile("red.global.add.v4.f32 [%0], {%1, %2, %3, %4};"
                 :: "l"(addr), "f"(a), "f"(b), "f"(c), "f"(d) : "memory");
}

// -------------------- small elementwise kernels --------------------
__global__ void deg_init(float* deg, int n) {
    int i = blockIdx.x * blockDim.x + threadIdx.x;
    if (i < n) deg[i] = 1.0f;
}

__global__ void deg_accum(const int* __restrict__ col, const float* __restrict__ ew,
                          float* deg, int E) {
    int e = blockIdx.x * blockDim.x + threadIdx.x;
    if (e < E) atomicAdd(&deg[col[e]], ew[e]);
}

__global__ void deg_rsqrt(const float* __restrict__ deg, float* dinv, int n) {
    int i = blockIdx.x * blockDim.x + threadIdx.x;
    if (i < n) {
        float d = deg[i];
        dinv[i] = d > 0.f ? rsqrtf(d) : 0.f;
    }
}

// dst[i,:] = dinv[i]^2 * src[i,:]   (self-loop term)
__global__ void selfloop_init(const float4* __restrict__ src, float4* __restrict__ dst,
                              const float* __restrict__ dinv, int n_nodes, int d4) {
    long idx = (long)blockIdx.x * blockDim.x + threadIdx.x;
    long total = (long)n_nodes * d4;
    if (idx >= total) return;
    int node = (int)(idx / d4);
    float s = dinv[node]; s = s * s;
    float4 v = src[idx];
    dst[idx] = make_float4(s * v.x, s * v.y, s * v.z, s * v.w);
}

// -------------------- edge aggregation (warp per edge, v4 reductions) -------
template <int D>
__global__ void agg_edges(const float4* __restrict__ src, float4* __restrict__ dst,
                          const int* __restrict__ row, const int* __restrict__ col,
                          const float* __restrict__ ew, const float* __restrict__ dinv,
                          int E) {
    int e = (int)(((long)blockIdx.x * blockDim.x + threadIdx.x) >> 5);
    if (e >= E) return;
    int lane = threadIdx.x & 31;
    int r = row[e], c = col[e];
    float s = dinv[r] * ew[e] * dinv[c];
    const float4* srow = src + (size_t)r * (D / 4);
    float4* drow = dst + (size_t)c * (D / 4);
#pragma unroll
    for (int i = 0; i < D / 128; i++) {
        int q = lane + i * 32;
        float4 v = srow[q];
        red_add_v4((float*)(drow + q), s * v.x, s * v.y, s * v.z, s * v.w);
    }
}

// -------------------- SGEMM 128x128x8, double-buffered smem -----------------
__global__ __launch_bounds__(256)
void sgemm_kernel(const float* __restrict__ A, const float* __restrict__ B,
                  float* __restrict__ C, int M, int N, int K,
                  const float* __restrict__ bias, const float* __restrict__ alpha) {
    constexpr int BM = 128, BN = 128, BK = 8, TM = 8, TN = 8;
    __shared__ float As[2][BK][BM];
    __shared__ float Bs[2][BK][BN];

    const int tid  = threadIdx.x;
    const int crow = tid / (BN / TN);   // 0..15
    const int ccol = tid % (BN / TN);   // 0..15

    const float* Ab = A + (size_t)blockIdx.y * BM * K;
    const float* Bb = B + (size_t)blockIdx.x * BN;

    const int arow = tid >> 1;
    const int ak   = (tid & 1) * 4;
    const int brow = tid >> 5;
    const int bcol = (tid & 31) * 4;

    float acc[TM][TN] = {};

    // load tile 0
    float4 a0 = *(const float4*)(Ab + (size_t)arow * K + ak);
    float4 b0 = *(const float4*)(Bb + (size_t)brow * N + bcol);
    As[0][ak + 0][arow] = a0.x; As[0][ak + 1][arow] = a0.y;
    As[0][ak + 2][arow] = a0.z; As[0][ak + 3][arow] = a0.w;
    *(float4*)&Bs[0][brow][bcol] = b0;
    __syncthreads();

    int buf = 0;
    for (int k0 = 0; k0 < K; k0 += BK) {
        float4 an, bn;
        const bool more = (k0 + BK) < K;
        if (more) {
            an = *(const float4*)(Ab + (size_t)arow * K + k0 + BK + ak);
            bn = *(const float4*)(Bb + (size_t)(k0 + BK + brow) * N + bcol);
        }
#pragma unroll
        for (int k = 0; k < BK; k++) {
            float ar[TM], br[TN];
            *(float4*)&ar[0] = *(const float4*)&As[buf][k][crow * TM];
            *(float4*)&ar[4] = *(const float4*)&As[buf][k][crow * TM + 4];
            *(float4*)&br[0] = *(const float4*)&Bs[buf][k][ccol * TN];
            *(float4*)&br[4] = *(const float4*)&Bs[buf][k][ccol * TN + 4];
#pragma unroll
            for (int i = 0; i < TM; i++)
#pragma unroll
                for (int j = 0; j < TN; j++)
                    acc[i][j] = fmaf(ar[i], br[j], acc[i][j]);
        }
        if (more) {
            int nb = buf ^ 1;
            As[nb][ak + 0][arow] = an.x; As[nb][ak + 1][arow] = an.y;
            As[nb][ak + 2][arow] = an.z; As[nb][ak + 3][arow] = an.w;
            *(float4*)&Bs[nb][brow][bcol] = bn;
            __syncthreads();
            buf = nb;
        }
    }

    const float al = alpha ? alpha[0] : 0.f;
    float* Cb = C + (size_t)blockIdx.y * BM * N + (size_t)blockIdx.x * BN;
#pragma unroll
    for (int i = 0; i < TM; i++) {
        const int r = crow * TM + i;
#pragma unroll
        for (int j = 0; j < TN; j += 4) {
            const int c = ccol * TN + j;
            float4 v = make_float4(acc[i][j], acc[i][j + 1], acc[i][j + 2], acc[i][j + 3]);
            if (bias) {
                const int gc = blockIdx.x * BN + c;
                v.x += bias[gc + 0]; v.y += bias[gc + 1];
                v.z += bias[gc + 2]; v.w += bias[gc + 3];
                v.x = v.x >= 0.f ? v.x : al * v.x;
                v.y = v.y >= 0.f ? v.y : al * v.y;
                v.z = v.z >= 0.f ? v.z : al * v.z;
                v.w = v.w >= 0.f ? v.w : al * v.w;
            }
            *(float4*)(Cb + (size_t)r * N + c) = v;
        }
    }
}

// out = prelu(out + b2)
__global__ void finalize_kernel(float4* __restrict__ out, const float* __restrict__ b2,
                                const float* __restrict__ alpha, long n4) {
    long i = (long)blockIdx.x * blockDim.x + threadIdx.x;
    if (i >= n4) return;
    float4 v = out[i];
    int d = (int)((i * 4) & (H2 - 1));
    float a = alpha[0];
    v.x += b2[d + 0]; v.y += b2[d + 1]; v.z += b2[d + 2]; v.w += b2[d + 3];
    v.x = v.x >= 0.f ? v.x : a * v.x;
    v.y = v.y >= 0.f ? v.y : a * v.y;
    v.z = v.z >= 0.f ? v.z : a * v.z;
    v.w = v.w >= 0.f ? v.w : a * v.w;
    out[i] = v;
}

// -------------------- launch --------------------
extern "C" void kernel_launch(void* const* d_in, const int* in_sizes, int n_in,
                              void* d_out, int out_size) {
    const float* x     = (const float*)d_in[0];
    const float* ew    = (const float*)d_in[1];
    const float* W1    = (const float*)d_in[2];
    const float* b1    = (const float*)d_in[3];
    const float* W2    = (const float*)d_in[4];
    const float* b2    = (const float*)d_in[5];
    const float* alpha = (const float*)d_in[6];
    const int*   eidx  = (const int*)  d_in[7];

    const int E = in_sizes[1];
    const int N = in_sizes[0] / IN_DIM;
    const int* row = eidx;
    const int* col = eidx + E;

    float* out = (float*)d_out;

    float *deg, *dinv, *agg1, *feat1, *xw2;
    cudaGetSymbolAddress((void**)&deg,   g_deg);
    cudaGetSymbolAddress((void**)&dinv,  g_dinv);
    cudaGetSymbolAddress((void**)&agg1,  g_agg1);
    cudaGetSymbolAddress((void**)&feat1, g_feat1);
    cudaGetSymbolAddress((void**)&xw2,   g_xw2);

    // 1) degrees + dinv
    deg_init<<<(N + 255) / 256, 256>>>(deg, N);
    deg_accum<<<(E + 255) / 256, 256>>>(col, ew, deg, E);
    deg_rsqrt<<<(N + 255) / 256, 256>>>(deg, dinv, N);

    // 2) layer-1 aggregation at D=256: agg1 = A_norm @ x
    {
        long n4 = (long)N * (IN_DIM / 4);
        selfloop_init<<<(int)((n4 + 255) / 256), 256>>>((const float4*)x, (float4*)agg1, dinv, N, IN_DIM / 4);
        long threads = (long)E * 32;
        agg_edges<IN_DIM><<<(int)((threads + 255) / 256), 256>>>(
            (const float4*)x, (float4*)agg1, row, col, ew, dinv, E);
    }

    // 3) GEMM1: feat1 = prelu(agg1 @ W1 + b1)
    {
        dim3 grid(H1 / 128, M_PAD / 128);
        sgemm_kernel<<<grid, 256>>>(agg1, W1, feat1, M_PAD, H1, IN_DIM, b1, alpha);
    }

    // 4) GEMM2: xw2 = feat1 @ W2
    {
        dim3 grid(H2 / 128, M_PAD / 128);
        sgemm_kernel<<<grid, 256>>>(feat1, W2, xw2, M_PAD, H2, H1, nullptr, nullptr);
    }

    // 5) layer-2 aggregation at D=128 into d_out
    {
        long n4 = (long)N * (H2 / 4);
        selfloop_init<<<(int)((n4 + 255) / 256), 256>>>((const float4*)xw2, (float4*)out, dinv, N, H2 / 4);
        long threads = (long)E * 32;
        agg_edges<H2><<<(int)((threads + 255) / 256), 256>>>(
            (const float4*)xw2, (float4*)out, row, col, ew, dinv, E);
    }

    // 6) out = prelu(out + b2)
    {
        long n4 = (long)N * (H2 / 4);
        finalize_kernel<<<(int)((n4 + 255) / 256), 256>>>((float4*)out, b2, alpha, n4);
    }
}